// round 6
// baseline (speedup 1.0000x reference)
#include <cuda_runtime.h>
#include <cstdint>

#define Nn    100000
#define F     256
#define FS    32
#define FA    288
#define NLY   4
#define NG    50
#define NE_UP 400000
#define NE_L  300000
#define NE_TOT (NE_UP + 8 * NE_L)
#define SCAN_L (9 * Nn)
#define SCAN_BLK 1024
#define SCAN_NB ((SCAN_L + SCAN_BLK - 1) / SCAN_BLK)

// ---------------- device scratch ----------------
__device__ float g_x[(size_t)Nn * F];
__device__ float g_pi[(size_t)Nn * F];
__device__ float g_st[(size_t)Nn * F];       // compact conv-output staging
__device__ float g_agg16[(size_t)Nn * 16];
__device__ float g_dinv[(size_t)SCAN_L];
__device__ int   g_hist[(size_t)SCAN_L];
__device__ int   g_rp[(size_t)SCAN_L + 1];
__device__ int   g_col[(size_t)NE_TOT];
__device__ float g_we[(size_t)NE_TOT];
__device__ int   g_bsum[SCAN_NB];
__device__ int   g_boff[SCAN_NB];
__device__ int   g_total;
__device__ int   g_rows[(size_t)NLY * Nn];
__device__ int   g_cnt[NLY];
__device__ float g_WtIn[(size_t)256 * FA];
__device__ float g_WtFw[(size_t)256 * FA];
__device__ float g_WtUp[(size_t)256 * 16];

__device__ __forceinline__ uint32_t f2tf32(float f) {
    uint32_t r; asm("cvt.rna.tf32.f32 %0, %1;" : "=r"(r) : "f"(f)); return r;
}
__device__ __forceinline__ void mma_tf32(float* d, const uint32_t* a, const uint32_t* b) {
    asm volatile(
        "mma.sync.aligned.m16n8k8.row.col.f32.tf32.tf32.f32 "
        "{%0,%1,%2,%3}, {%4,%5,%6,%7}, {%8,%9}, {%0,%1,%2,%3};"
        : "+f"(d[0]), "+f"(d[1]), "+f"(d[2]), "+f"(d[3])
        : "r"(a[0]), "r"(a[1]), "r"(a[2]), "r"(a[3]), "r"(b[0]), "r"(b[1]));
}
__device__ __forceinline__ float4 fmaf4(float4 a, float w, float4 v) {
    a.x = fmaf(w, v.x, a.x); a.y = fmaf(w, v.y, a.y);
    a.z = fmaf(w, v.z, a.z); a.w = fmaf(w, v.w, a.w);
    return a;
}
__device__ __forceinline__ uint4 tf4(float4 v) {
    return make_uint4(f2tf32(v.x), f2tf32(v.y), f2tf32(v.z), f2tf32(v.w));
}

// ---------------- CSR build ----------------
__global__ void k_hist0() {
    int i = blockIdx.x * blockDim.x + threadIdx.x;
    if (i < SCAN_L) g_hist[i] = 0;
    if (i < NLY) g_cnt[i] = 0;
}
__global__ void k_hist(const int* __restrict__ dst, int nE, int slot) {
    int i = blockIdx.x * blockDim.x + threadIdx.x;
    if (i >= nE) return;
    atomicAdd(&g_hist[(size_t)slot * Nn + dst[i]], 1);
}
__global__ void k_scan1() {
    __shared__ int ws[8];
    int t = threadIdx.x;
    int base = blockIdx.x * SCAN_BLK + t * 4;
    int v[4], s = 0;
#pragma unroll
    for (int j = 0; j < 4; j++) {
        v[j] = (base + j < SCAN_L) ? g_hist[base + j] : 0;
        s += v[j];
    }
    int lane = t & 31, w = t >> 5;
    int inc = s;
#pragma unroll
    for (int o = 1; o < 32; o <<= 1) {
        int x = __shfl_up_sync(0xffffffffu, inc, o);
        if (lane >= o) inc += x;
    }
    if (lane == 31) ws[w] = inc;
    __syncthreads();
    if (t < 8) {
        int x = ws[t];
#pragma unroll
        for (int o = 1; o < 8; o <<= 1) {
            int y = __shfl_up_sync(0xffu, x, o);
            if (t >= o) x += y;
        }
        ws[t] = x;
    }
    __syncthreads();
    int run = inc - s + (w > 0 ? ws[w - 1] : 0);
#pragma unroll
    for (int j = 0; j < 4; j++) {
        if (base + j < SCAN_L) g_rp[base + j] = run;
        run += v[j];
    }
    __syncthreads();
    if (t == 255) g_bsum[blockIdx.x] = ws[7];
}
__global__ void k_scan2() {
    __shared__ int ws[32];
    int t = threadIdx.x;
    int v = (t < SCAN_NB) ? g_bsum[t] : 0;
    int lane = t & 31, w = t >> 5;
    int inc = v;
#pragma unroll
    for (int o = 1; o < 32; o <<= 1) {
        int x = __shfl_up_sync(0xffffffffu, inc, o);
        if (lane >= o) inc += x;
    }
    if (lane == 31) ws[w] = inc;
    __syncthreads();
    if (t < 32) {
        int x = ws[t];
#pragma unroll
        for (int o = 1; o < 32; o <<= 1) {
            int y = __shfl_up_sync(0xffffffffu, x, o);
            if (t >= o) x += y;
        }
        ws[t] = x;
    }
    __syncthreads();
    int excl = inc - v + (w > 0 ? ws[w - 1] : 0);
    if (t < SCAN_NB) g_boff[t] = excl;
    if (t == SCAN_NB - 1) g_total = excl + v;
}
__global__ void k_scan3() {
    int t = threadIdx.x;
    int off = g_boff[blockIdx.x];
    int base = blockIdx.x * SCAN_BLK + t * 4;
#pragma unroll
    for (int j = 0; j < 4; j++)
        if (base + j < SCAN_L) g_rp[base + j] += off;
    if (blockIdx.x == 0 && t == 0) g_rp[SCAN_L] = g_total;
}
__global__ void k_dinv() {
    int i = blockIdx.x * blockDim.x + threadIdx.x;
    if (i < SCAN_L) g_dinv[i] = rsqrtf((float)(g_hist[i] + 1));
}
__global__ void k_cursor() {
    int i = blockIdx.x * blockDim.x + threadIdx.x;
    if (i < SCAN_L) g_hist[i] = g_rp[i];
}
__global__ void k_fill(const int* __restrict__ src, const int* __restrict__ dst,
                       int nE, int slot) {
    int e = blockIdx.x * blockDim.x + threadIdx.x;
    if (e >= nE) return;
    int d = dst[e], s = src[e];
    int pos = atomicAdd(&g_hist[(size_t)slot * Nn + d], 1);
    g_col[pos] = s;
    g_we[pos] = g_dinv[(size_t)slot * Nn + s];
}
__global__ void k_build(const int* __restrict__ layers) {
    int n = blockIdx.x * blockDim.x + threadIdx.x;
    if (n >= Nn) return;
    int il = layers[n];
    int p = atomicAdd(&g_cnt[il], 1);
    g_rows[(size_t)il * Nn + p] = n;
}
__global__ void k_transpose(const float* __restrict__ W, float* __restrict__ Wt, int K) {
    int i = blockIdx.x * blockDim.x + threadIdx.x;
    if (i >= K * 256) return;
    int k = i >> 8, n = i & 255;
    Wt[(size_t)n * K + k] = W[i];
}

// ---------------- up conv ----------------
__global__ void k_up_gather(const float* __restrict__ x16) {
    int i = blockIdx.x * blockDim.x + threadIdx.x;
    if (i >= Nn * 4) return;
    int n = i >> 2, q = i & 3;
    float dd = g_dinv[n];
    int r0 = g_rp[n], r1 = g_rp[n + 1];
    float4 a = ((const float4*)(x16 + (size_t)n * 16))[q];
    a.x *= dd; a.y *= dd; a.z *= dd; a.w *= dd;
    for (int e = r0; e < r1; e++) {
        int s = g_col[e];
        float wgt = g_we[e];
        a = fmaf4(a, wgt, ((const float4*)(x16 + (size_t)s * 16))[q]);
    }
    a.x *= dd; a.y *= dd; a.z *= dd; a.w *= dd;
    ((float4*)(g_agg16 + (size_t)n * 16))[q] = a;
}

#define ASTRIDE 36
__global__ void __launch_bounds__(256)
k_mma_gemm_up(const float* __restrict__ bias) {
    __shared__ uint32_t As[128 * ASTRIDE];
    __shared__ uint32_t Bs[128 * ASTRIDE];
    int row0 = blockIdx.x * 128;
    int colb = blockIdx.y * 128;
    int tid = threadIdx.x, wid = tid >> 5, lane = tid & 31;
    int wm = (wid >> 2) * 64, wn = (wid & 3) * 32;
    int q = lane >> 2, t = lane & 3;

    float acc[4][4][4];
#pragma unroll
    for (int i = 0; i < 4; i++)
#pragma unroll
        for (int j = 0; j < 4; j++)
#pragma unroll
            for (int k = 0; k < 4; k++) acc[i][j][k] = 0.f;
    {
        int idx = tid;
        for (int i = 0; i < 2; i++) {
            int e = idx + i * 256;
            int m = e >> 2, k4 = e & 3;
            int g = row0 + m;
            uint4 v = make_uint4(0, 0, 0, 0);
            if (g < Nn) v = tf4(*(const float4*)(g_agg16 + (size_t)g * 16 + k4 * 4));
            *(uint4*)(&As[m * ASTRIDE + k4 * 4]) = v;
        }
        for (int i = 0; i < 2; i++) {
            int e = idx + i * 256;
            int n = e >> 2, k4 = e & 3;
            float4 f = *(const float4*)(g_WtUp + (size_t)(colb + n) * 16 + k4 * 4);
            *(uint4*)(&Bs[n * ASTRIDE + k4 * 4]) = tf4(f);
        }
    }
    __syncthreads();
#pragma unroll
    for (int ks = 0; ks < 2; ks++) {
        int kc = ks * 8;
        uint32_t af[4][4];
#pragma unroll
        for (int mt = 0; mt < 4; mt++) {
            int r = wm + mt * 16 + q;
            af[mt][0] = As[r * ASTRIDE + kc + t];
            af[mt][1] = As[(r + 8) * ASTRIDE + kc + t];
            af[mt][2] = As[r * ASTRIDE + kc + t + 4];
            af[mt][3] = As[(r + 8) * ASTRIDE + kc + t + 4];
        }
        uint32_t bf[4][2];
#pragma unroll
        for (int nt = 0; nt < 4; nt++) {
            int n = wn + nt * 8 + q;
            bf[nt][0] = Bs[n * ASTRIDE + kc + t];
            bf[nt][1] = Bs[n * ASTRIDE + kc + t + 4];
        }
#pragma unroll
        for (int mt = 0; mt < 4; mt++)
#pragma unroll
            for (int nt = 0; nt < 4; nt++)
                mma_tf32(acc[mt][nt], af[mt], bf[nt]);
    }
#pragma unroll
    for (int mt = 0; mt < 4; mt++) {
        int n0 = row0 + wm + mt * 16 + q;
        int n1 = n0 + 8;
#pragma unroll
        for (int nt = 0; nt < 4; nt++) {
            int col = colb + wn + nt * 8 + t * 2;
            float b0 = bias[col], b1 = bias[col + 1];
            if (n0 < Nn)
                *(float2*)(g_x + (size_t)n0 * F + col) =
                    make_float2(acc[mt][nt][0] + b0, acc[mt][nt][1] + b1);
            if (n1 < Nn)
                *(float2*)(g_x + (size_t)n1 * F + col) =
                    make_float2(acc[mt][nt][2] + b0, acc[mt][nt][3] + b1);
        }
    }
}

// ---------------- FUSED conv: gather -> SMEM tf32 -> MMA -> staging ----------------
// 512 thr, tile M=64 x N=256, K=288. Output: to_pi ? g_pi[n] : g_st[compact idx].
// NEVER writes g_x (read by gather) -> no intra-grid RAW hazard.
#define AS 292
#define BSS 36
#define SMEMC ((64 * AS + 256 * BSS) * 4)

__global__ void __launch_bounds__(512, 2)
k_conv(const float* __restrict__ stat, int slot, int mask_il,
       const float* __restrict__ Wt, const float* __restrict__ bias, int to_pi) {
    extern __shared__ uint32_t sm[];
    uint32_t* Asm = sm;               // 64 x AS
    uint32_t* Bsm = sm + 64 * AS;     // 256 x BSS

    int cnt = (mask_il >= 0) ? g_cnt[mask_il] : Nn;
    const int* list = (mask_il >= 0) ? (g_rows + (size_t)mask_il * Nn) : nullptr;
    int row0 = blockIdx.x * 64;
    if (row0 >= cnt) return;

    int tid = threadIdx.x, wid = tid >> 5, lane = tid & 31;
    size_t sb = (size_t)slot * Nn;

    // ===== phase 1: gather 64 rows of agg[288] into Asm (tf32); 16 warps x 4 rows =====
#pragma unroll 1
    for (int i = 0; i < 4; i++) {
        int r = wid * 4 + i;
        int g = row0 + r;
        uint32_t* arow = Asm + r * AS;
        if (g >= cnt) {
            uint4 z = make_uint4(0, 0, 0, 0);
            *(uint4*)(arow + lane * 4) = z;
            *(uint4*)(arow + (lane + 32) * 4) = z;
            if (lane < 8) *(uint4*)(arow + (lane + 64) * 4) = z;
            continue;
        }
        int n = list ? list[g] : g;
        float dd = g_dinv[sb + n];
        int e = g_rp[sb + n], e1 = g_rp[sb + n + 1];
        const float4* xn = (const float4*)(g_x + (size_t)n * F);
        float4 a0 = xn[lane], a1 = xn[lane + 32];
        float4 a2 = make_float4(0.f, 0.f, 0.f, 0.f);
        if (lane < 8) a2 = ((const float4*)(stat + (size_t)n * FS))[lane];
        a0.x *= dd; a0.y *= dd; a0.z *= dd; a0.w *= dd;
        a1.x *= dd; a1.y *= dd; a1.z *= dd; a1.w *= dd;
        a2.x *= dd; a2.y *= dd; a2.z *= dd; a2.w *= dd;
        int sn = 0; float wn_ = 0.f;
        if (e < e1) { sn = g_col[e]; wn_ = g_we[e]; }
        while (e < e1) {
            int s = sn; float wgt = wn_;
            if (e + 1 < e1) { sn = g_col[e + 1]; wn_ = g_we[e + 1]; }
            const float4* xs = (const float4*)(g_x + (size_t)s * F);
            a0 = fmaf4(a0, wgt, xs[lane]);
            a1 = fmaf4(a1, wgt, xs[lane + 32]);
            if (lane < 8)
                a2 = fmaf4(a2, wgt, ((const float4*)(stat + (size_t)s * FS))[lane]);
            e++;
        }
        a0.x *= dd; a0.y *= dd; a0.z *= dd; a0.w *= dd;
        a1.x *= dd; a1.y *= dd; a1.z *= dd; a1.w *= dd;
        a2.x *= dd; a2.y *= dd; a2.z *= dd; a2.w *= dd;
        *(uint4*)(arow + lane * 4) = tf4(a0);
        *(uint4*)(arow + (lane + 32) * 4) = tf4(a1);
        if (lane < 8) *(uint4*)(arow + (lane + 64) * 4) = tf4(a2);
    }
    __syncthreads();

    // ===== phase 2: MMA, 16 warps = 2M x 8N, warp tile 32x32 =====
    int wm = (wid >> 3) * 32;
    int wn = (wid & 7) * 32;
    int q = lane >> 2, t = lane & 3;

    float acc[2][4][4];
#pragma unroll
    for (int i = 0; i < 2; i++)
#pragma unroll
        for (int j = 0; j < 4; j++)
#pragma unroll
            for (int k = 0; k < 4; k++) acc[i][j][k] = 0.f;

#pragma unroll 1
    for (int kt = 0; kt < FA; kt += 32) {
#pragma unroll
        for (int i = 0; i < 4; i++) {
            int idx = tid + i * 512;
            int n = idx >> 3, k4 = idx & 7;
            float4 f = *(const float4*)(Wt + (size_t)n * FA + kt + k4 * 4);
            *(uint4*)(&Bsm[n * BSS + k4 * 4]) = tf4(f);
        }
        __syncthreads();
#pragma unroll
        for (int ks = 0; ks < 4; ks++) {
            int kc = kt + ks * 8;
            uint32_t af[2][4];
#pragma unroll
            for (int mt = 0; mt < 2; mt++) {
                int r = wm + mt * 16 + q;
                af[mt][0] = Asm[r * AS + kc + t];
                af[mt][1] = Asm[(r + 8) * AS + kc + t];
                af[mt][2] = Asm[r * AS + kc + t + 4];
                af[mt][3] = Asm[(r + 8) * AS + kc + t + 4];
            }
            uint32_t bf[4][2];
#pragma unroll
            for (int nt = 0; nt < 4; nt++) {
                int n = wn + nt * 8 + q;
                bf[nt][0] = Bsm[n * BSS + ks * 8 + t];
                bf[nt][1] = Bsm[n * BSS + ks * 8 + t + 4];
            }
#pragma unroll
            for (int mt = 0; mt < 2; mt++)
#pragma unroll
                for (int nt = 0; nt < 4; nt++)
                    mma_tf32(acc[mt][nt], af[mt], bf[nt]);
        }
        __syncthreads();
    }

    // ===== phase 3: epilogue -> g_pi (full) or compact g_st (masked) =====
#pragma unroll
    for (int mt = 0; mt < 2; mt++) {
        int g0 = row0 + wm + mt * 16 + q;
        int g1 = g0 + 8;
        float* o0 = to_pi ? (g_pi + (size_t)g0 * F) : (g_st + (size_t)g0 * F);
        float* o1 = to_pi ? (g_pi + (size_t)g1 * F) : (g_st + (size_t)g1 * F);
#pragma unroll
        for (int nt = 0; nt < 4; nt++) {
            int col = wn + nt * 8 + t * 2;
            float b0 = bias[col], b1 = bias[col + 1];
            if (g0 < cnt)
                *(float2*)(o0 + col) =
                    make_float2(acc[mt][nt][0] + b0, acc[mt][nt][1] + b1);
            if (g1 < cnt)
                *(float2*)(o1 + col) =
                    make_float2(acc[mt][nt][2] + b0, acc[mt][nt][3] + b1);
        }
    }
}

// commit: g_x[rows(il)[idx]] = g_st[idx]
__global__ void k_commit(int il) {
    int c = threadIdx.x & 63, r = threadIdx.x >> 6;   // 256 thr = 4 rows x 64 f4
    int idx = blockIdx.x * 4 + r;
    if (idx >= g_cnt[il]) return;
    int n = g_rows[(size_t)il * Nn + idx];
    ((float4*)(g_x + (size_t)n * F))[c] = ((const float4*)(g_st + (size_t)idx * F))[c];
}

// ---------------- misc ----------------
__global__ void k_copy_rows(int il) {
    int c = threadIdx.x % 64, r = threadIdx.x / 64;
    int idx = blockIdx.x * 4 + r;
    if (idx >= g_cnt[il]) return;
    int n = g_rows[(size_t)il * Nn + idx];
    ((float4*)(g_x + (size_t)n * F))[c] = ((const float4*)(g_pi + (size_t)n * F))[c];
}
__global__ void k_relu4() {
    int i = blockIdx.x * blockDim.x + threadIdx.x;
    if (i >= Nn * F / 4) return;
    float4* p = (float4*)g_x;
    float4 v = p[i];
    v.x = fmaxf(v.x, 0.f); v.y = fmaxf(v.y, 0.f);
    v.z = fmaxf(v.z, 0.f); v.w = fmaxf(v.w, 0.f);
    p[i] = v;
}
__global__ void k_pool_init(const float* __restrict__ bl, float* __restrict__ out) {
    int g = threadIdx.x;
    if (g < NG) out[g] = bl[0];
}
__global__ void k_pool(const int* __restrict__ batch, const float* __restrict__ Wl,
                       float* __restrict__ out) {
    int w = (blockIdx.x * blockDim.x + threadIdx.x) >> 5;
    int lane = threadIdx.x & 31;
    if (w >= Nn) return;
    const float* xr = g_x + (size_t)w * F;
    float s = 0.f;
    for (int c = lane; c < F; c += 32) s += xr[c] * Wl[c];
#pragma unroll
    for (int o = 16; o; o >>= 1) s += __shfl_down_sync(0xffffffffu, s, o);
    if (lane == 0) atomicAdd(&out[batch[w]], s);
}

// ---------------- orchestration ----------------
extern "C" void kernel_launch(void* const* d_in, const int* in_sizes, int n_in,
                              void* d_out, int out_size) {
    const float* x16    = (const float*)d_in[0];
    const float* stat   = (const float*)d_in[1];
    const int*   eidx   = (const int*)d_in[2];
    const int*   einner = (const int*)d_in[3];
    const int*   efw    = (const int*)d_in[4];
    const int*   layers = (const int*)d_in[6];
    const int*   batch  = (const int*)d_in[7];
    const float* W_up  = (const float*)d_in[8];
    const float* b_up  = (const float*)d_in[9];
    const float* W_in  = (const float*)d_in[10];
    const float* b_in  = (const float*)d_in[11];
    const float* W_fw  = (const float*)d_in[12];
    const float* b_fw  = (const float*)d_in[13];
    const float* W_lin = (const float*)d_in[14];
    const float* b_lin = (const float*)d_in[15];
    float* out = (float*)d_out;

    float* d_WtIn; cudaGetSymbolAddress((void**)&d_WtIn, g_WtIn);
    float* d_WtFw; cudaGetSymbolAddress((void**)&d_WtFw, g_WtFw);
    float* d_WtUp; cudaGetSymbolAddress((void**)&d_WtUp, g_WtUp);

    cudaFuncSetAttribute(k_conv, cudaFuncAttributeMaxDynamicSharedMemorySize, SMEMC);

    // ---- CSR build ----
    k_hist0<<<(SCAN_L + 255) / 256, 256>>>();
    k_hist<<<(NE_UP + 255) / 256, 256>>>(eidx + NE_UP, NE_UP, 0);
    for (int il = 0; il < NLY; il++)
        k_hist<<<(NE_L + 255) / 256, 256>>>(einner + (size_t)il * 2 * NE_L + NE_L, NE_L, 1 + il);
    for (int il = 0; il < NLY; il++)
        k_hist<<<(NE_L + 255) / 256, 256>>>(efw + (size_t)il * 2 * NE_L + NE_L, NE_L, 5 + il);
    k_scan1<<<SCAN_NB, 256>>>();
    k_scan2<<<1, 1024>>>();
    k_scan3<<<SCAN_NB, 256>>>();
    k_dinv<<<(SCAN_L + 255) / 256, 256>>>();
    k_cursor<<<(SCAN_L + 255) / 256, 256>>>();
    k_fill<<<(NE_UP + 255) / 256, 256>>>(eidx, eidx + NE_UP, NE_UP, 0);
    for (int il = 0; il < NLY; il++)
        k_fill<<<(NE_L + 255) / 256, 256>>>(einner + (size_t)il * 2 * NE_L,
                                            einner + (size_t)il * 2 * NE_L + NE_L, NE_L, 1 + il);
    for (int il = 0; il < NLY; il++)
        k_fill<<<(NE_L + 255) / 256, 256>>>(efw + (size_t)il * 2 * NE_L,
                                            efw + (size_t)il * 2 * NE_L + NE_L, NE_L, 5 + il);
    k_build<<<(Nn + 255) / 256, 256>>>(layers);
    k_transpose<<<(FA * 256 + 255) / 256, 256>>>(W_in, d_WtIn, FA);
    k_transpose<<<(FA * 256 + 255) / 256, 256>>>(W_fw, d_WtFw, FA);
    k_transpose<<<(16 * 256 + 255) / 256, 256>>>(W_up, d_WtUp, 16);

    const int GXC = (Nn + 63) / 64;       // conv tiles (max)
    const int GC  = (Nn + 3) / 4;         // commit grid (max)

    // ---- up conv ----
    k_up_gather<<<(Nn * 4 + 255) / 256, 256>>>(x16);
    k_mma_gemm_up<<<dim3((Nn + 127) / 128, 2), 256>>>(b_up);

    auto conv = [&](int slot, int mask, const float* Wt, const float* bb, int to_pi) {
        k_conv<<<GXC, 512, SMEMC>>>(stat, slot, mask, Wt, bb, to_pi);
        if (!to_pi) k_commit<<<GC, 256>>>(mask);
    };

    for (int p = 0; p < 2; p++) {
        for (int il = 0; il < 3; il++) {
            conv(1 + il, il, d_WtIn, b_in, 0);          // inner -> rows(il)
            conv(5 + il, il + 1, d_WtFw, b_fw, 0);      // fw    -> rows(il+1)
        }
        conv(4, -1, d_WtIn, b_in, 1);                   // full -> pi (no commit)
        k_copy_rows<<<GC, 256>>>(3);
        k_relu4<<<(Nn * F / 4 + 255) / 256, 256>>>();
        for (int il = 3; il >= 0; il--) {
            if (il >= 1) k_copy_rows<<<GC, 256>>>(il - 1);
            conv(1 + il, il, d_WtIn, b_in, 0);
        }
        k_relu4<<<(Nn * F / 4 + 255) / 256, 256>>>();
    }

    k_pool_init<<<1, 64>>>(b_lin, out);
    k_pool<<<(Nn * 32 + 255) / 256, 256>>>(batch, W_lin, out);
}